// round 6
// baseline (speedup 1.0000x reference)
#include <cuda_runtime.h>

// ---------------------------------------------------------------------------
// GlimpseNetwork fused pipeline.  B=4096, H=128, G=14, patches 14/28/56/112.
// All operands pre-permuted to tf32/mma fragment-major; GEMM hot loops are
// pure LDG.128->STS.128 + LDS.128 + MMA.
// ---------------------------------------------------------------------------

#define BATCH 4096
#define HIMG  128
#define PHI_DIM 784

// Scratch (device globals; no cudaMalloc allowed)
// fragment-major activations/weights
__device__ __align__(16) float g_phif[PHI_DIM * BATCH];    // tf32 frag-major (A of gemm1)
__device__ __align__(16) float g_h1wf[BATCH * 128];        // f32 frag-major (A of gemm2 what)
__device__ __align__(16) float g_h1lf[BATCH * 128];        // f32 frag-major (A of gemm2 where)
__device__ __align__(16) float g_W1f[PHI_DIM * 128];       // tf32 frag-major B
__device__ __align__(16) float g_W2wf[128 * 256];
__device__ __align__(16) float g_W2lf[128 * 256];
// row-major layer-2 outputs
__device__ __align__(16) float g_h2w[BATCH * 256];
__device__ __align__(16) float g_h2l[BATCH * 256];
// per-block column partials (deterministic: no atomics)
__device__ float g_p1w_s[128 * 128], g_p1w_q[128 * 128];
__device__ float g_p1l_s[32 * 128],  g_p1l_q[32 * 128];
__device__ float g_p2w_s[64 * 256],  g_p2w_q[64 * 256];
__device__ float g_p2l_s[64 * 256],  g_p2l_q[64 * 256];
// fused BN transforms: h_norm = fma(h, scale, shift)
__device__ float g_s1w[128], g_t1w[128], g_s1l[128], g_t1l[128];
__device__ float g_s2w[256], g_t2w[256], g_s2l[256], g_t2l[256];

__device__ __forceinline__ unsigned f2tf(float v) {
    unsigned r;
    asm("cvt.rna.tf32.f32 %0, %1;" : "=r"(r) : "f"(v));
    return r;
}

__device__ __forceinline__ void mma_tf32(float* d, const unsigned* a, const unsigned* b) {
    asm volatile(
        "mma.sync.aligned.m16n8k8.row.col.f32.tf32.tf32.f32 "
        "{%0,%1,%2,%3}, {%4,%5,%6,%7}, {%8,%9}, {%0,%1,%2,%3};"
        : "+f"(d[0]), "+f"(d[1]), "+f"(d[2]), "+f"(d[3])
        : "r"(a[0]), "r"(a[1]), "r"(a[2]), "r"(a[3]), "r"(b[0]), "r"(b[1]));
}

// ---------------------------------------------------------------------------
// B (weights, N x K row-major input) -> tf32 fragment-major.
// uint4 frag unit at lane l covers [b(k,n), b(k+4,n), b(k,n+8), b(k+4,n+8)],
// l = (n&7)*4 + (k&3).
// ---------------------------------------------------------------------------
__device__ __forceinline__ void conv_frag(const float* __restrict__ W,
                                          float* __restrict__ Wf,
                                          int Kw, int Nw, int tid0, int nthreads)
{
    int total = Kw * Nw;
    for (int e = tid0; e < total; e += nthreads) {
        int kk = e / Nw, n = e - kk * Nw;
        int pos = (kk >> 4) * (Nw * 16)
                + (((kk >> 3) & 1) * (Nw >> 4) + (n >> 4)) * 128
                + (((n & 7) << 2) + (kk & 3)) * 4
                + (((n >> 3) & 1) << 1) + ((kk >> 2) & 1);
        Wf[pos] = __uint_as_float(f2tf(W[e]));
    }
}

// A fragment-major word index for element (m, k), M rows total.
// uint4 unit order: [a(m,k), a(m+8,k), a(m,k+4), a(m+8,k+4)], l=(m&7)*4+(k&3).
__device__ __forceinline__ size_t posA(int m, int k, int M)
{
    return (size_t)(k >> 4) * (M * 16)
         + (size_t)(((k >> 3) & 1) * (M >> 4) + (m >> 4)) * 128
         + (((m & 7) << 2) + (k & 3)) * 4
         + ((m >> 3) & 1) + (((k >> 2) & 1) << 1);
}

// ---------------------------------------------------------------------------
// 1) Foveate: 16 samples per block, 512 threads. Computes pooled pyramid into
//    a 16x784 SMEM stage, then writes phi as tf32 fragment-major (coalesced).
//    Aux blocks: where-layer1 (frag-major out) + weight conversions.
//    Grid: [0,256) samples, [256,288) where1, [288,336) W1, [336,344) W2w,
//    [344,352) W2l.
// ---------------------------------------------------------------------------
#define FOV_SMEM ((3192 + 196 + 16 * 785) * 4)

__global__ void __launch_bounds__(512) foveate_kernel(
    const float* __restrict__ x,
    const float* __restrict__ loc,
    const float* __restrict__ lW1,
    const float* __restrict__ lb1,
    const float* __restrict__ wW1,
    const float* __restrict__ wW2,
    const float* __restrict__ lW2)
{
    extern __shared__ float dynsmem[];
    int tid = threadIdx.x;

    if (blockIdx.x >= 256) {
        int bx = blockIdx.x - 256;
        if (bx < 32) {
            // where-layer1: block handles 128 rows; thread owns column c,
            // 4 row-groups of 32. Frag-major raw-f32 output + stats partials.
            float* wrs = dynsmem;
            float* wrq = dynsmem + 512;
            int c = tid & 127;
            int g = tid >> 7;
            int r0 = bx * 128 + g * 32;
            float w0 = lW1[c], w1 = lW1[128 + c], bb = lb1[c];
            float s = 0.0f, q = 0.0f;
            for (int r = r0; r < r0 + 32; r++) {
                float2 l = ((const float2*)loc)[r];
                float v = fmaf(l.x, w0, fmaf(l.y, w1, bb));
                g_h1lf[posA(r, c, BATCH)] = v;
                s += v;
                q += v * v;
            }
            wrs[tid] = s;
            wrq[tid] = q;
            __syncthreads();
            if (tid < 128) {
                g_p1l_s[bx * 128 + tid] = wrs[tid] + wrs[tid + 128] + wrs[tid + 256] + wrs[tid + 384];
                g_p1l_q[bx * 128 + tid] = wrq[tid] + wrq[tid + 128] + wrq[tid + 256] + wrq[tid + 384];
            }
        } else if (bx < 80) {
            conv_frag(wW1, g_W1f, PHI_DIM, 128, (bx - 32) * 512 + tid, 48 * 512);
        } else if (bx < 88) {
            conv_frag(wW2, g_W2wf, 128, 256, (bx - 80) * 512 + tid, 8 * 512);
        } else if (bx < 96) {
            conv_frag(lW2, g_W2lf, 128, 256, (bx - 88) * 512 + tid, 8 * 512);
        }
        return;
    }

    float* pooled = dynsmem;            // 56*57 = 3192
    float* center = dynsmem + 3192;     // 196
    float* stage  = dynsmem + 3388;     // 16*785

    for (int s = 0; s < 16; s++) {
        int b = blockIdx.x * 16 + s;
        float lx = loc[2 * b + 0];
        float ly = loc[2 * b + 1];
        int cx = (int)(0.5f * ((lx + 1.0f) * 128.0f));
        int cy = (int)(0.5f * ((ly + 1.0f) * 128.0f));
        int row0 = cy - 56;
        int col0 = cx - 56;
        const float* __restrict__ img = x + (size_t)b * HIMG * HIMG;

        for (int idx = tid; idx < 56 * 56; idx += 512) {
            int pr = idx / 56;
            int pc = idx - pr * 56;
            int r = row0 + 2 * pr;
            int c = col0 + 2 * pc;
            float sm = 0.0f;
            bool r0ok = (unsigned)r < 128u, r1ok = (unsigned)(r + 1) < 128u;
            bool c0ok = (unsigned)c < 128u, c1ok = (unsigned)(c + 1) < 128u;
            if (r0ok && c0ok) sm += img[r * HIMG + c];
            if (r0ok && c1ok) sm += img[r * HIMG + c + 1];
            if (r1ok && c0ok) sm += img[(r + 1) * HIMG + c];
            if (r1ok && c1ok) sm += img[(r + 1) * HIMG + c + 1];
            pooled[pr * 57 + pc] = sm * 0.25f;
        }
        if (tid < 196) {
            int i = tid / 14;
            int j = tid - i * 14;
            int r = row0 + 49 + i;
            int c = col0 + 49 + j;
            float v = 0.0f;
            if ((unsigned)r < 128u && (unsigned)c < 128u) v = img[r * HIMG + c];
            center[tid] = v;
        }
        __syncthreads();

        for (int o = tid; o < PHI_DIM; o += 512) {
            int p = o / 196;
            int rem = o - p * 196;
            int i = rem / 14;
            int j = rem - i * 14;
            float v;
            if (p == 0) {
                v = center[rem];
            } else if (p == 1) {
                v = pooled[(21 + i) * 57 + 21 + j];
            } else if (p == 2) {
                int base = (14 + 2 * i) * 57 + 14 + 2 * j;
                v = (pooled[base] + pooled[base + 1] +
                     pooled[base + 57] + pooled[base + 58]) * 0.25f;
            } else {
                int base = (4 * i) * 57 + 4 * j;
                float sm = 0.0f;
                #pragma unroll
                for (int di = 0; di < 4; di++)
                    #pragma unroll
                    for (int dj = 0; dj < 4; dj++)
                        sm += pooled[base + di * 57 + dj];
                v = sm * (1.0f / 16.0f);
            }
            stage[s * 785 + o] = v;
        }
        __syncthreads();   // protect pooled/center before next sample's loads
    }

    // fragment write: 49 chunks x 2 k8 = 98 frags x 32 lanes
    for (int u = tid; u < 98 * 32; u += 512) {
        int l = u & 31;
        int f = u >> 5;
        int chunk = f >> 1;
        int k8 = f & 1;
        int kk = chunk * 16 + k8 * 8 + (l & 3);
        int r = l >> 2;
        uint4 o;
        o.x = f2tf(stage[r * 785 + kk]);
        o.y = f2tf(stage[(r + 8) * 785 + kk]);
        o.z = f2tf(stage[r * 785 + kk + 4]);
        o.w = f2tf(stage[(r + 8) * 785 + kk + 4]);
        ((uint4*)g_phif)[(size_t)chunk * 16384 + (size_t)(k8 * 256 + blockIdx.x) * 32 + l] = o;
    }
}

// ---------------------------------------------------------------------------
// 2) Fragment-major pipelined tf32 MMA GEMM. 256 thr = 8 warps (2m x 4n).
//    A path: LDG.128 frag -> (optional BN/ReLU/cvt) -> STS.128 (conflict-free).
//    FRAGOUT: epilogue emits fragment-major raw f32 (+stats); else row-major.
// ---------------------------------------------------------------------------
template <bool TA, bool FRAGOUT, int K, int N, int BM, int BN, int WM, int WN>
__device__ __forceinline__ void gemm_body(const uint4* __restrict__ Af,
                                          const float4* __restrict__ Bf,
                                          const float* __restrict__ bias,
                                          const float* __restrict__ sA,
                                          const float* __restrict__ tA,
                                          float* __restrict__ Cout,
                                          float* __restrict__ ps,
                                          float* __restrict__ pq,
                                          int mb, int nb)
{
    constexpr int NB16 = BN / 16;
    constexpr int STAGE_A = BM * 16;       // floats per stage
    constexpr int STAGE_B = BN * 16;
    constexpr int STAGE = STAGE_A + STAGE_B;
    constexpr int CSS = BN + 4;
    constexpr int BUFSZ = (2 * STAGE > BM * CSS) ? 2 * STAGE : BM * CSS;
    constexpr int STEPS = K / 16;
    constexpr int SK = TA ? K : 1;
    constexpr int AUNITS = BM * 4;         // uint4 units per A stage

    __shared__ __align__(16) float buf[BUFSZ];
    __shared__ float rs[256], rq[256];
    __shared__ float sSc[SK], sSh[SK];

    int tid = threadIdx.x;
    int lane = tid & 31;
    int wid = tid >> 5;
    int wn = wid & 3;
    int wm = wid >> 2;
    int m0 = mb * BM;
    int n0 = nb * BN;

    if (TA) {
        if (tid < K) { sSc[tid] = sA[tid]; sSh[tid] = tA[tid]; }
    }
    __syncthreads();

    uint4  aReg;
    float4 bReg[BN / 64];

    auto ldA = [&](int step) {
        if (tid < AUNITS) {
            int f = tid >> 5, l = tid & 31;
            int k8 = f / (BM / 16), mt = f % (BM / 16);
            aReg = Af[(size_t)step * 16384 + (size_t)(k8 * 256 + (m0 >> 4) + mt) * 32 + l];
        }
    };
    auto ldB = [&](int step) {
        const float4* src = Bf + (size_t)step * (N * 4);
        #pragma unroll
        for (int e = 0; e < BN / 64; e++) {
            int u = tid + e * 256;
            int k8 = u / (NB16 * 32);
            int rem = u - k8 * (NB16 * 32);
            bReg[e] = src[k8 * (N / 16) * 32 + (n0 / 16) * 32 + rem];
        }
    };
    auto stA = [&](float* As, int step) {
        if (tid < AUNITS) {
            if (!TA) {
                ((uint4*)As)[tid] = aReg;
            } else {
                int f = tid >> 5, l = tid & 31;
                int k8 = f / (BM / 16);
                int kk = step * 16 + k8 * 8 + (l & 3);
                float sc0 = sSc[kk],     sh0 = sSh[kk];
                float sc4 = sSc[kk + 4], sh4 = sSh[kk + 4];
                uint4 o;
                o.x = f2tf(fmaxf(fmaf(__uint_as_float(aReg.x), sc0, sh0), 0.0f));
                o.y = f2tf(fmaxf(fmaf(__uint_as_float(aReg.y), sc0, sh0), 0.0f));
                o.z = f2tf(fmaxf(fmaf(__uint_as_float(aReg.z), sc4, sh4), 0.0f));
                o.w = f2tf(fmaxf(fmaf(__uint_as_float(aReg.w), sc4, sh4), 0.0f));
                ((uint4*)As)[tid] = o;
            }
        }
    };
    auto stB = [&](float* Bs) {
        #pragma unroll
        for (int e = 0; e < BN / 64; e++)
            ((float4*)Bs)[tid + e * 256] = bReg[e];
    };

    float acc[WM][WN][4];
    #pragma unroll
    for (int i = 0; i < WM; i++)
        #pragma unroll
        for (int f = 0; f < WN; f++)
            #pragma unroll
            for (int v = 0; v < 4; v++) acc[i][f][v] = 0.0f;

    auto compute = [&](const float* As, const float* Bs) {
        #pragma unroll
        for (int k8 = 0; k8 < 2; k8++) {
            unsigned a[WM][4];
            #pragma unroll
            for (int i = 0; i < WM; i++)
                *(uint4*)a[i] = *(const uint4*)&((const unsigned*)As)[
                    (k8 * (BM / 16) + wm * WM + i) * 128 + lane * 4];
            #pragma unroll
            for (int j = 0; j < WN / 2; j++) {
                uint4 bb = *(const uint4*)&((const unsigned*)Bs)[
                    (k8 * NB16 + wn * (WN / 2) + j) * 128 + lane * 4];
                unsigned bl[2] = {bb.x, bb.y};
                unsigned bh[2] = {bb.z, bb.w};
                #pragma unroll
                for (int i = 0; i < WM; i++) {
                    mma_tf32(acc[i][2 * j],     a[i], bl);
                    mma_tf32(acc[i][2 * j + 1], a[i], bh);
                }
            }
        }
    };

    // pipeline
    ldA(0); ldB(0);
    stA(buf, 0); stB(buf + STAGE_A);
    if (STEPS > 1) { ldA(1); ldB(1); }
    __syncthreads();

    for (int s = 0; s < STEPS; s++) {
        int cur = s & 1, nxt = cur ^ 1;
        float* curBuf = buf + cur * STAGE;
        if (s + 1 < STEPS) {
            float* nxtBuf = buf + nxt * STAGE;
            stA(nxtBuf, s + 1);
            stB(nxtBuf + STAGE_A);
        }
        if (s + 2 < STEPS) { ldA(s + 2); ldB(s + 2); }
        compute(curBuf, curBuf + STAGE_A);
        __syncthreads();
    }

    // fragments -> Cs
    float* Cs = buf;
    #pragma unroll
    for (int i = 0; i < WM; i++) {
        int row = (wm * WM + i) * 16 + (lane >> 2);
        #pragma unroll
        for (int f = 0; f < WN; f++) {
            int cb = wn * WN * 8 + f * 8 + 2 * (lane & 3);
            *(float2*)&Cs[row * CSS + cb]       = make_float2(acc[i][f][0], acc[i][f][1]);
            *(float2*)&Cs[(row + 8) * CSS + cb] = make_float2(acc[i][f][2], acc[i][f][3]);
        }
    }
    __syncthreads();

    // bias + stats (+ optional store-back for frag pass)
    {
        constexpr int RPT = BM * BN / 256;
        int c = tid & (BN - 1);
        int h = tid / BN;
        float bb = bias[n0 + c];
        float s = 0.0f, q = 0.0f;
        #pragma unroll
        for (int i = 0; i < RPT; i++) {
            int r = h * RPT + i;
            float v = Cs[r * CSS + c] + bb;
            if (FRAGOUT) Cs[r * CSS + c] = v;
            else         Cout[(size_t)(m0 + r) * N + n0 + c] = v;
            s += v;
            q += v * v;
        }
        rs[tid] = s;
        rq[tid] = q;
    }
    __syncthreads();
    if (tid < BN) {
        float s = 0.0f, q = 0.0f;
        #pragma unroll
        for (int g = 0; g < 256 / BN; g++) { s += rs[g * BN + tid]; q += rq[g * BN + tid]; }
        ps[mb * N + n0 + tid] = s;
        pq[mb * N + n0 + tid] = q;
    }

    if (FRAGOUT) {
        __syncthreads();
        // emit raw-f32 fragment-major (consumed as A by next GEMM, M=4096)
        constexpr int UNITS = BM * BN / 4;
        #pragma unroll
        for (int i2 = 0; i2 < UNITS / 256; i2++) {
            int u = tid + i2 * 256;
            int l = u & 31;
            int f = u >> 5;
            int cl = f / (2 * (BM / 16));
            int rf = f % (2 * (BM / 16));
            int k8 = rf / (BM / 16);
            int mt = rf % (BM / 16);
            int nl = cl * 16 + k8 * 8 + (l & 3);
            int rl = mt * 16 + (l >> 2);
            float4 o = make_float4(Cs[rl * CSS + nl],       Cs[(rl + 8) * CSS + nl],
                                   Cs[rl * CSS + nl + 4],   Cs[(rl + 8) * CSS + nl + 4]);
            ((float4*)Cout)[(size_t)(n0 / 16 + cl) * 16384 +
                            (size_t)(k8 * 256 + (m0 >> 4) + mt) * 32 + l] = o;
        }
    }
}

// layer-1 what GEMM: phi_frag(784x4096) -> h1w frag.  BM=32 BN=64, grid (2,128).
__global__ void __launch_bounds__(256) gemm1_kernel(const float* __restrict__ b1)
{
    gemm_body<false, true, PHI_DIM, 128, 32, 64, 1, 2>(
        (const uint4*)g_phif, (const float4*)g_W1f, b1, nullptr, nullptr,
        g_h1wf, g_p1w_s, g_p1w_q, blockIdx.y, blockIdx.x);
}

// layer-2 GEMMs merged: z=0 what, z=1 where.  BM=64 BN=64, grid (4,64,2).
__global__ void __launch_bounds__(256) gemm2_kernel(const float* __restrict__ wb2,
                                                    const float* __restrict__ lb2)
{
    if (blockIdx.z == 0)
        gemm_body<true, false, 128, 256, 64, 64, 2, 2>(
            (const uint4*)g_h1wf, (const float4*)g_W2wf, wb2, g_s1w, g_t1w,
            g_h2w, g_p2w_s, g_p2w_q, blockIdx.y, blockIdx.x);
    else
        gemm_body<true, false, 128, 256, 64, 64, 2, 2>(
            (const uint4*)g_h1lf, (const float4*)g_W2lf, lb2, g_s1l, g_t1l,
            g_h2l, g_p2l_s, g_p2l_q, blockIdx.y, blockIdx.x);
}

// ---------------------------------------------------------------------------
// 3) Parallel finalize: one block per column.
// ---------------------------------------------------------------------------
__device__ __forceinline__ void reduce_finalize(float s, float q, int c,
                                                const float* __restrict__ gam,
                                                const float* __restrict__ bet,
                                                float* __restrict__ sc_out,
                                                float* __restrict__ sh_out)
{
    __shared__ float rs[128], rq[128];
    rs[threadIdx.x] = s;
    rq[threadIdx.x] = q;
    __syncthreads();
    #pragma unroll
    for (int off = 64; off >= 32; off >>= 1) {
        if (threadIdx.x < off) {
            rs[threadIdx.x] += rs[threadIdx.x + off];
            rq[threadIdx.x] += rq[threadIdx.x + off];
        }
        __syncthreads();
    }
    if (threadIdx.x < 32) {
        float ss = rs[threadIdx.x];
        float qq = rq[threadIdx.x];
        #pragma unroll
        for (int off = 16; off > 0; off >>= 1) {
            ss += __shfl_down_sync(0xffffffffu, ss, off);
            qq += __shfl_down_sync(0xffffffffu, qq, off);
        }
        if (threadIdx.x == 0) {
            float m = ss * (1.0f / BATCH);
            float var = qq * (1.0f / BATCH) - m * m;
            float r = rsqrtf(var + 1e-5f);
            float sc = r * gam[c];
            sc_out[c] = sc;
            sh_out[c] = bet[c] - m * sc;
        }
    }
}

__global__ void finalize1_kernel(const float* __restrict__ g1w, const float* __restrict__ be1w,
                                 const float* __restrict__ g1l, const float* __restrict__ be1l)
{
    int t = threadIdx.x;
    if (blockIdx.x < 128) {
        int c = blockIdx.x;
        reduce_finalize(g_p1w_s[t * 128 + c], g_p1w_q[t * 128 + c],
                        c, g1w, be1w, g_s1w, g_t1w);
    } else {
        int c = blockIdx.x - 128;
        float s = (t < 32) ? g_p1l_s[t * 128 + c] : 0.0f;
        float q = (t < 32) ? g_p1l_q[t * 128 + c] : 0.0f;
        reduce_finalize(s, q, c, g1l, be1l, g_s1l, g_t1l);
    }
}

__global__ void finalize2_kernel(const float* __restrict__ g2w, const float* __restrict__ be2w,
                                 const float* __restrict__ g2l, const float* __restrict__ be2l)
{
    int t = threadIdx.x;
    if (blockIdx.x < 256) {
        int c = blockIdx.x;
        float s = (t < 64) ? g_p2w_s[t * 256 + c] : 0.0f;
        float q = (t < 64) ? g_p2w_q[t * 256 + c] : 0.0f;
        reduce_finalize(s, q, c, g2w, be2w, g_s2w, g_t2w);
    } else {
        int c = blockIdx.x - 256;
        float s = (t < 64) ? g_p2l_s[t * 256 + c] : 0.0f;
        float q = (t < 64) ? g_p2l_q[t * 256 + c] : 0.0f;
        reduce_finalize(s, q, c, g2l, be2l, g_s2l, g_t2l);
    }
}

// ---------------------------------------------------------------------------
// 4) Final: out = relu( BN(h2w) + BN(h2l) )
// ---------------------------------------------------------------------------
__global__ void final_kernel(float* __restrict__ out)
{
    int idx = blockIdx.x * 256 + threadIdx.x;
    int c = idx & 255;
    float vw = fmaf(g_h2w[idx], g_s2w[c], g_t2w[c]);
    float vl = fmaf(g_h2l[idx], g_s2l[c], g_t2l[c]);
    float v = vw + vl;
    out[idx] = v > 0.0f ? v : 0.0f;
}

// ---------------------------------------------------------------------------
extern "C" void kernel_launch(void* const* d_in, const int* in_sizes, int n_in,
                              void* d_out, int out_size)
{
    const float* x    = (const float*)d_in[0];
    const float* loc  = (const float*)d_in[1];
    const float* wW1  = (const float*)d_in[2];
    const float* wb1  = (const float*)d_in[3];
    const float* wg1  = (const float*)d_in[4];
    const float* wbe1 = (const float*)d_in[5];
    const float* wW2  = (const float*)d_in[6];
    const float* wb2  = (const float*)d_in[7];
    const float* wg2  = (const float*)d_in[8];
    const float* wbe2 = (const float*)d_in[9];
    const float* lW1  = (const float*)d_in[10];
    const float* lb1  = (const float*)d_in[11];
    const float* lg1  = (const float*)d_in[12];
    const float* lbe1 = (const float*)d_in[13];
    const float* lW2  = (const float*)d_in[14];
    const float* lb2  = (const float*)d_in[15];
    const float* lg2  = (const float*)d_in[16];
    const float* lbe2 = (const float*)d_in[17];
    float* out = (float*)d_out;

    static int smem_set = 0;
    if (!smem_set) {
        cudaFuncSetAttribute(foveate_kernel,
                             cudaFuncAttributeMaxDynamicSharedMemorySize, FOV_SMEM);
        smem_set = 1;
    }

    // 1) foveate (16 samples/block) + where1 + weight conversions
    foveate_kernel<<<352, 512, FOV_SMEM>>>(x, loc, lW1, lb1, wW1, wW2, lW2);

    // 2) what layer1 -> h1w frag (+ stats partials)
    {
        dim3 grid(2, BATCH / 32);
        gemm1_kernel<<<grid, 256>>>(wb1);
    }

    // 3) finalize layer-1 BN params
    finalize1_kernel<<<256, 128>>>(wg1, wbe1, lg1, lbe1);

    // 4) both layer-2 GEMMs (BN+ReLU fused into A path, stats partials)
    {
        dim3 grid(4, BATCH / 64, 2);
        gemm2_kernel<<<grid, 256>>>(wb2, lb2);
    }

    // 5) finalize layer-2 BN params
    finalize2_kernel<<<512, 128>>>(wg2, wbe2, lg2, lbe2);

    // 6) final add + relu
    final_kernel<<<BATCH * 256 / 256, 256>>>(out);
}

// round 7
// speedup vs baseline: 1.2945x; 1.2945x over previous
#include <cuda_runtime.h>

// ---------------------------------------------------------------------------
// GlimpseNetwork fused pipeline.  B=4096, H=128, G=14, patches 14/28/56/112.
// Fragment-major tf32 MMA GEMMs; per-sample foveate writes phi frag-major.
// ---------------------------------------------------------------------------

#define BATCH 4096
#define HIMG  128
#define PHI_DIM 784

// Scratch (device globals; no cudaMalloc allowed)
__device__ __align__(16) float g_phif[PHI_DIM * BATCH];    // tf32 frag-major (A of gemm1)
__device__ __align__(16) float g_h1wf[BATCH * 128];        // f32 frag-major (A of gemm2 what)
__device__ __align__(16) float g_h1lf[BATCH * 128];        // f32 frag-major (A of gemm2 where)
__device__ __align__(16) float g_W1f[PHI_DIM * 128];       // tf32 frag-major B
__device__ __align__(16) float g_W2wf[128 * 256];
__device__ __align__(16) float g_W2lf[128 * 256];
__device__ __align__(16) float g_h2w[BATCH * 256];
__device__ __align__(16) float g_h2l[BATCH * 256];
// per-block column partials (deterministic: no atomics)
__device__ float g_p1w_s[128 * 128], g_p1w_q[128 * 128];
__device__ float g_p1l_s[32 * 128],  g_p1l_q[32 * 128];
__device__ float g_p2w_s[128 * 256], g_p2w_q[128 * 256];
__device__ float g_p2l_s[128 * 256], g_p2l_q[128 * 256];
// fused BN transforms: h_norm = fma(h, scale, shift)
__device__ float g_s1w[128], g_t1w[128], g_s1l[128], g_t1l[128];
__device__ float g_s2w[256], g_t2w[256], g_s2l[256], g_t2l[256];

__device__ __forceinline__ unsigned f2tf(float v) {
    unsigned r;
    asm("cvt.rna.tf32.f32 %0, %1;" : "=r"(r) : "f"(v));
    return r;
}

__device__ __forceinline__ void mma_tf32(float* d, const unsigned* a, const unsigned* b) {
    asm volatile(
        "mma.sync.aligned.m16n8k8.row.col.f32.tf32.tf32.f32 "
        "{%0,%1,%2,%3}, {%4,%5,%6,%7}, {%8,%9}, {%0,%1,%2,%3};"
        : "+f"(d[0]), "+f"(d[1]), "+f"(d[2]), "+f"(d[3])
        : "r"(a[0]), "r"(a[1]), "r"(a[2]), "r"(a[3]), "r"(b[0]), "r"(b[1]));
}

// B (weights, K x N row-major input) -> tf32 fragment-major.
__device__ __forceinline__ void conv_frag(const float* __restrict__ W,
                                          float* __restrict__ Wf,
                                          int Kw, int Nw, int tid0, int nthreads)
{
    int total = Kw * Nw;
    for (int e = tid0; e < total; e += nthreads) {
        int kk = e / Nw, n = e - kk * Nw;
        int pos = (kk >> 4) * (Nw * 16)
                + (((kk >> 3) & 1) * (Nw >> 4) + (n >> 4)) * 128
                + (((n & 7) << 2) + (kk & 3)) * 4
                + (((n >> 3) & 1) << 1) + ((kk >> 2) & 1);
        Wf[pos] = __uint_as_float(f2tf(W[e]));
    }
}

// A fragment-major word index for element (m, k), M rows total.
__device__ __forceinline__ size_t posA(int m, int k, int M)
{
    return (size_t)(k >> 4) * (M * 16)
         + (size_t)(((k >> 3) & 1) * (M >> 4) + (m >> 4)) * 128
         + (((m & 7) << 2) + (k & 3)) * 4
         + ((m >> 3) & 1) + (((k >> 2) & 1) << 1);
}

// ---------------------------------------------------------------------------
// 1) Foveate: one sample per block (4096 blocks, 256 threads), 2x2-pooled
//    pyramid in SMEM, phi written tf32 fragment-major (scatter).
//    Aux work folded into low blocks: 0..31 where-layer1 (frag out),
//    32..79 W1 conv, 80..87 W2w conv, 88..95 W2l conv.
// ---------------------------------------------------------------------------
__global__ void __launch_bounds__(256) foveate_kernel(
    const float* __restrict__ x,
    const float* __restrict__ loc,
    const float* __restrict__ lW1,
    const float* __restrict__ lb1,
    const float* __restrict__ wW1,
    const float* __restrict__ wW2,
    const float* __restrict__ lW2)
{
    __shared__ float pooled[56 * 57];
    __shared__ float center[196];
    __shared__ float wrs[256], wrq[256];
    int tid = threadIdx.x;
    int b = blockIdx.x;

    float lx = loc[2 * b + 0];
    float ly = loc[2 * b + 1];
    int cx = (int)(0.5f * ((lx + 1.0f) * 128.0f));
    int cy = (int)(0.5f * ((ly + 1.0f) * 128.0f));
    int row0 = cy - 56;
    int col0 = cx - 56;
    const float* __restrict__ img = x + (size_t)b * HIMG * HIMG;

    for (int idx = tid; idx < 56 * 56; idx += 256) {
        int pr = idx / 56;
        int pc = idx - pr * 56;
        int r = row0 + 2 * pr;
        int c = col0 + 2 * pc;
        float sm = 0.0f;
        bool r0ok = (unsigned)r < 128u, r1ok = (unsigned)(r + 1) < 128u;
        bool c0ok = (unsigned)c < 128u, c1ok = (unsigned)(c + 1) < 128u;
        if (r0ok && c0ok) sm += img[r * HIMG + c];
        if (r0ok && c1ok) sm += img[r * HIMG + c + 1];
        if (r1ok && c0ok) sm += img[(r + 1) * HIMG + c];
        if (r1ok && c1ok) sm += img[(r + 1) * HIMG + c + 1];
        pooled[pr * 57 + pc] = sm * 0.25f;
    }
    if (tid < 196) {
        int i = tid / 14;
        int j = tid - i * 14;
        int r = row0 + 49 + i;
        int c = col0 + 49 + j;
        float v = 0.0f;
        if ((unsigned)r < 128u && (unsigned)c < 128u) v = img[r * HIMG + c];
        center[tid] = v;
    }
    __syncthreads();

    for (int o = tid; o < PHI_DIM; o += 256) {
        int p = o / 196;
        int rem = o - p * 196;
        int i = rem / 14;
        int j = rem - i * 14;
        float v;
        if (p == 0) {
            v = center[rem];
        } else if (p == 1) {
            v = pooled[(21 + i) * 57 + 21 + j];
        } else if (p == 2) {
            int base = (14 + 2 * i) * 57 + 14 + 2 * j;
            v = (pooled[base] + pooled[base + 1] +
                 pooled[base + 57] + pooled[base + 58]) * 0.25f;
        } else {
            int base = (4 * i) * 57 + 4 * j;
            float sm = 0.0f;
            #pragma unroll
            for (int di = 0; di < 4; di++)
                #pragma unroll
                for (int dj = 0; dj < 4; dj++)
                    sm += pooled[base + di * 57 + dj];
            v = sm * (1.0f / 16.0f);
        }
        // fragment-major tf32 scatter write
        g_phif[posA(b, o, BATCH)] = __uint_as_float(f2tf(v));
    }

    // ---- folded aux work ----
    if (b < 32) {
        // where-layer1: block handles 128 rows, 2 row-halves; frag-major out.
        int c = tid & 127;
        int half = tid >> 7;
        int r0 = b * 128 + half * 64;
        float w0 = lW1[c], w1 = lW1[128 + c], bb = lb1[c];
        float s = 0.0f, q = 0.0f;
        for (int r = r0; r < r0 + 64; r++) {
            float2 l = ((const float2*)loc)[r];
            float v = fmaf(l.x, w0, fmaf(l.y, w1, bb));
            g_h1lf[posA(r, c, BATCH)] = v;
            s += v;
            q += v * v;
        }
        wrs[tid] = s;
        wrq[tid] = q;
        __syncthreads();
        if (tid < 128) {
            g_p1l_s[b * 128 + tid] = wrs[tid] + wrs[tid + 128];
            g_p1l_q[b * 128 + tid] = wrq[tid] + wrq[tid + 128];
        }
    } else if (b < 80) {
        conv_frag(wW1, g_W1f, PHI_DIM, 128, (b - 32) * 256 + tid, 48 * 256);
    } else if (b < 88) {
        conv_frag(wW2, g_W2wf, 128, 256, (b - 80) * 256 + tid, 8 * 256);
    } else if (b < 96) {
        conv_frag(lW2, g_W2lf, 128, 256, (b - 88) * 256 + tid, 8 * 256);
    }
}

// ---------------------------------------------------------------------------
// 2) Fragment-major pipelined tf32 MMA GEMM. 256 thr = 8 warps (2m x 4n).
//    A path: LDG.128 frag -> (optional BN/ReLU/cvt) -> STS.128 (conflict-free).
//    FRAGOUT: epilogue emits fragment-major raw f32 (+stats); else row-major.
// ---------------------------------------------------------------------------
template <bool TA, bool FRAGOUT, int K, int N, int BM, int BN, int WM, int WN>
__device__ __forceinline__ void gemm_body(const uint4* __restrict__ Af,
                                          const float4* __restrict__ Bf,
                                          const float* __restrict__ bias,
                                          const float* __restrict__ sA,
                                          const float* __restrict__ tA,
                                          float* __restrict__ Cout,
                                          float* __restrict__ ps,
                                          float* __restrict__ pq,
                                          int mb, int nb)
{
    constexpr int NB16 = BN / 16;
    constexpr int STAGE_A = BM * 16;       // floats per stage
    constexpr int STAGE_B = BN * 16;
    constexpr int STAGE = STAGE_A + STAGE_B;
    constexpr int CSS = BN + 4;
    constexpr int BUFSZ = (2 * STAGE > BM * CSS) ? 2 * STAGE : BM * CSS;
    constexpr int STEPS = K / 16;
    constexpr int SK = TA ? K : 1;
    constexpr int AUNITS = BM * 4;         // uint4 units per A stage

    __shared__ __align__(16) float buf[BUFSZ];
    __shared__ float rs[256], rq[256];
    __shared__ float sSc[SK], sSh[SK];

    int tid = threadIdx.x;
    int lane = tid & 31;
    int wid = tid >> 5;
    int wn = wid & 3;
    int wm = wid >> 2;
    int m0 = mb * BM;
    int n0 = nb * BN;

    if (TA) {
        if (tid < K) { sSc[tid] = sA[tid]; sSh[tid] = tA[tid]; }
    }
    __syncthreads();

    uint4  aReg;
    float4 bReg[BN / 64];

    auto ldA = [&](int step) {
        if (tid < AUNITS) {
            int f = tid >> 5, l = tid & 31;
            int k8 = f / (BM / 16), mt = f % (BM / 16);
            aReg = Af[(size_t)step * 16384 + (size_t)(k8 * 256 + (m0 >> 4) + mt) * 32 + l];
        }
    };
    auto ldB = [&](int step) {
        const float4* src = Bf + (size_t)step * (N * 4);
        #pragma unroll
        for (int e = 0; e < BN / 64; e++) {
            int u = tid + e * 256;
            int k8 = u / (NB16 * 32);
            int rem = u - k8 * (NB16 * 32);
            bReg[e] = src[k8 * (N / 16) * 32 + (n0 / 16) * 32 + rem];
        }
    };
    auto stA = [&](float* As, int step) {
        if (tid < AUNITS) {
            if (!TA) {
                ((uint4*)As)[tid] = aReg;
            } else {
                int f = tid >> 5, l = tid & 31;
                int k8 = f / (BM / 16);
                int kk = step * 16 + k8 * 8 + (l & 3);
                float sc0 = sSc[kk],     sh0 = sSh[kk];
                float sc4 = sSc[kk + 4], sh4 = sSh[kk + 4];
                uint4 o;
                o.x = f2tf(fmaxf(fmaf(__uint_as_float(aReg.x), sc0, sh0), 0.0f));
                o.y = f2tf(fmaxf(fmaf(__uint_as_float(aReg.y), sc0, sh0), 0.0f));
                o.z = f2tf(fmaxf(fmaf(__uint_as_float(aReg.z), sc4, sh4), 0.0f));
                o.w = f2tf(fmaxf(fmaf(__uint_as_float(aReg.w), sc4, sh4), 0.0f));
                ((uint4*)As)[tid] = o;
            }
        }
    };
    auto stB = [&](float* Bs) {
        #pragma unroll
        for (int e = 0; e < BN / 64; e++)
            ((float4*)Bs)[tid + e * 256] = bReg[e];
    };

    float acc[WM][WN][4];
    #pragma unroll
    for (int i = 0; i < WM; i++)
        #pragma unroll
        for (int f = 0; f < WN; f++)
            #pragma unroll
            for (int v = 0; v < 4; v++) acc[i][f][v] = 0.0f;

    auto compute = [&](const float* As, const float* Bs) {
        #pragma unroll
        for (int k8 = 0; k8 < 2; k8++) {
            unsigned a[WM][4];
            #pragma unroll
            for (int i = 0; i < WM; i++)
                *(uint4*)a[i] = *(const uint4*)&((const unsigned*)As)[
                    (k8 * (BM / 16) + wm * WM + i) * 128 + lane * 4];
            #pragma unroll
            for (int j = 0; j < WN / 2; j++) {
                uint4 bb = *(const uint4*)&((const unsigned*)Bs)[
                    (k8 * NB16 + wn * (WN / 2) + j) * 128 + lane * 4];
                unsigned bl[2] = {bb.x, bb.y};
                unsigned bh[2] = {bb.z, bb.w};
                #pragma unroll
                for (int i = 0; i < WM; i++) {
                    mma_tf32(acc[i][2 * j],     a[i], bl);
                    mma_tf32(acc[i][2 * j + 1], a[i], bh);
                }
            }
        }
    };

    // pipeline
    ldA(0); ldB(0);
    stA(buf, 0); stB(buf + STAGE_A);
    if (STEPS > 1) { ldA(1); ldB(1); }
    __syncthreads();

    for (int s = 0; s < STEPS; s++) {
        int cur = s & 1, nxt = cur ^ 1;
        float* curBuf = buf + cur * STAGE;
        if (s + 1 < STEPS) {
            float* nxtBuf = buf + nxt * STAGE;
            stA(nxtBuf, s + 1);
            stB(nxtBuf + STAGE_A);
        }
        if (s + 2 < STEPS) { ldA(s + 2); ldB(s + 2); }
        compute(curBuf, curBuf + STAGE_A);
        __syncthreads();
    }

    // fragments -> Cs
    float* Cs = buf;
    #pragma unroll
    for (int i = 0; i < WM; i++) {
        int row = (wm * WM + i) * 16 + (lane >> 2);
        #pragma unroll
        for (int f = 0; f < WN; f++) {
            int cb = wn * WN * 8 + f * 8 + 2 * (lane & 3);
            *(float2*)&Cs[row * CSS + cb]       = make_float2(acc[i][f][0], acc[i][f][1]);
            *(float2*)&Cs[(row + 8) * CSS + cb] = make_float2(acc[i][f][2], acc[i][f][3]);
        }
    }
    __syncthreads();

    // bias + stats (+ optional store-back for frag pass)
    {
        constexpr int RPT = BM * BN / 256;
        int c = tid & (BN - 1);
        int h = tid / BN;
        float bb = bias[n0 + c];
        float s = 0.0f, q = 0.0f;
        #pragma unroll
        for (int i = 0; i < RPT; i++) {
            int r = h * RPT + i;
            float v = Cs[r * CSS + c] + bb;
            if (FRAGOUT) Cs[r * CSS + c] = v;
            else         Cout[(size_t)(m0 + r) * N + n0 + c] = v;
            s += v;
            q += v * v;
        }
        rs[tid] = s;
        rq[tid] = q;
    }
    __syncthreads();
    if (tid < BN) {
        float s = 0.0f, q = 0.0f;
        #pragma unroll
        for (int g = 0; g < 256 / BN; g++) { s += rs[g * BN + tid]; q += rq[g * BN + tid]; }
        ps[mb * N + n0 + tid] = s;
        pq[mb * N + n0 + tid] = q;
    }

    if (FRAGOUT) {
        __syncthreads();
        // emit raw-f32 fragment-major (consumed as A by next GEMM, M=4096)
        constexpr int UNITS = BM * BN / 4;
        #pragma unroll
        for (int i2 = 0; i2 < UNITS / 256; i2++) {
            int u = tid + i2 * 256;
            int l = u & 31;
            int f = u >> 5;
            int cl = f / (2 * (BM / 16));
            int rf = f % (2 * (BM / 16));
            int k8 = rf / (BM / 16);
            int mt = rf % (BM / 16);
            int nl = cl * 16 + k8 * 8 + (l & 3);
            int rl = mt * 16 + (l >> 2);
            float4 o = make_float4(Cs[rl * CSS + nl],       Cs[(rl + 8) * CSS + nl],
                                   Cs[rl * CSS + nl + 4],   Cs[(rl + 8) * CSS + nl + 4]);
            ((float4*)Cout)[(size_t)(n0 / 16 + cl) * 16384 +
                            (size_t)(k8 * 256 + (m0 >> 4) + mt) * 32 + l] = o;
        }
    }
}

// layer-1 what GEMM: phi_frag(784x4096) -> h1w frag.  BM=32 BN=64, grid (2,128).
__global__ void __launch_bounds__(256) gemm1_kernel(const float* __restrict__ b1)
{
    gemm_body<false, true, PHI_DIM, 128, 32, 64, 1, 2>(
        (const uint4*)g_phif, (const float4*)g_W1f, b1, nullptr, nullptr,
        g_h1wf, g_p1w_s, g_p1w_q, blockIdx.y, blockIdx.x);
}

// layer-2 GEMMs merged: z=0 what, z=1 where.  BM=32 BN=64, grid (4,128,2).
__global__ void __launch_bounds__(256) gemm2_kernel(const float* __restrict__ wb2,
                                                    const float* __restrict__ lb2)
{
    if (blockIdx.z == 0)
        gemm_body<true, false, 128, 256, 32, 64, 1, 2>(
            (const uint4*)g_h1wf, (const float4*)g_W2wf, wb2, g_s1w, g_t1w,
            g_h2w, g_p2w_s, g_p2w_q, blockIdx.y, blockIdx.x);
    else
        gemm_body<true, false, 128, 256, 32, 64, 1, 2>(
            (const uint4*)g_h1lf, (const float4*)g_W2lf, lb2, g_s1l, g_t1l,
            g_h2l, g_p2l_s, g_p2l_q, blockIdx.y, blockIdx.x);
}

// ---------------------------------------------------------------------------
// 3) Parallel finalize: one block per column.
// ---------------------------------------------------------------------------
__device__ __forceinline__ void reduce_finalize(float s, float q, int c,
                                                const float* __restrict__ gam,
                                                const float* __restrict__ bet,
                                                float* __restrict__ sc_out,
                                                float* __restrict__ sh_out)
{
    __shared__ float rs[128], rq[128];
    rs[threadIdx.x] = s;
    rq[threadIdx.x] = q;
    __syncthreads();
    #pragma unroll
    for (int off = 64; off >= 32; off >>= 1) {
        if (threadIdx.x < off) {
            rs[threadIdx.x] += rs[threadIdx.x + off];
            rq[threadIdx.x] += rq[threadIdx.x + off];
        }
        __syncthreads();
    }
    if (threadIdx.x < 32) {
        float ss = rs[threadIdx.x];
        float qq = rq[threadIdx.x];
        #pragma unroll
        for (int off = 16; off > 0; off >>= 1) {
            ss += __shfl_down_sync(0xffffffffu, ss, off);
            qq += __shfl_down_sync(0xffffffffu, qq, off);
        }
        if (threadIdx.x == 0) {
            float m = ss * (1.0f / BATCH);
            float var = qq * (1.0f / BATCH) - m * m;
            float r = rsqrtf(var + 1e-5f);
            float sc = r * gam[c];
            sc_out[c] = sc;
            sh_out[c] = bet[c] - m * sc;
        }
    }
}

__global__ void finalize1_kernel(const float* __restrict__ g1w, const float* __restrict__ be1w,
                                 const float* __restrict__ g1l, const float* __restrict__ be1l)
{
    int t = threadIdx.x;
    if (blockIdx.x < 128) {
        int c = blockIdx.x;
        reduce_finalize(g_p1w_s[t * 128 + c], g_p1w_q[t * 128 + c],
                        c, g1w, be1w, g_s1w, g_t1w);
    } else {
        int c = blockIdx.x - 128;
        float s = (t < 32) ? g_p1l_s[t * 128 + c] : 0.0f;
        float q = (t < 32) ? g_p1l_q[t * 128 + c] : 0.0f;
        reduce_finalize(s, q, c, g1l, be1l, g_s1l, g_t1l);
    }
}

__global__ void finalize2_kernel(const float* __restrict__ g2w, const float* __restrict__ be2w,
                                 const float* __restrict__ g2l, const float* __restrict__ be2l)
{
    int t = threadIdx.x;
    if (blockIdx.x < 256) {
        int c = blockIdx.x;
        reduce_finalize(g_p2w_s[t * 256 + c], g_p2w_q[t * 256 + c],
                        c, g2w, be2w, g_s2w, g_t2w);
    } else {
        int c = blockIdx.x - 256;
        reduce_finalize(g_p2l_s[t * 256 + c], g_p2l_q[t * 256 + c],
                        c, g2l, be2l, g_s2l, g_t2l);
    }
}

// ---------------------------------------------------------------------------
// 4) Final: out = relu( BN(h2w) + BN(h2l) )
// ---------------------------------------------------------------------------
__global__ void final_kernel(float* __restrict__ out)
{
    int idx = blockIdx.x * 256 + threadIdx.x;
    int c = idx & 255;
    float vw = fmaf(g_h2w[idx], g_s2w[c], g_t2w[c]);
    float vl = fmaf(g_h2l[idx], g_s2l[c], g_t2l[c]);
    float v = vw + vl;
    out[idx] = v > 0.0f ? v : 0.0f;
}

// ---------------------------------------------------------------------------
extern "C" void kernel_launch(void* const* d_in, const int* in_sizes, int n_in,
                              void* d_out, int out_size)
{
    const float* x    = (const float*)d_in[0];
    const float* loc  = (const float*)d_in[1];
    const float* wW1  = (const float*)d_in[2];
    const float* wb1  = (const float*)d_in[3];
    const float* wg1  = (const float*)d_in[4];
    const float* wbe1 = (const float*)d_in[5];
    const float* wW2  = (const float*)d_in[6];
    const float* wb2  = (const float*)d_in[7];
    const float* wg2  = (const float*)d_in[8];
    const float* wbe2 = (const float*)d_in[9];
    const float* lW1  = (const float*)d_in[10];
    const float* lb1  = (const float*)d_in[11];
    const float* lg1  = (const float*)d_in[12];
    const float* lbe1 = (const float*)d_in[13];
    const float* lW2  = (const float*)d_in[14];
    const float* lb2  = (const float*)d_in[15];
    const float* lg2  = (const float*)d_in[16];
    const float* lbe2 = (const float*)d_in[17];
    float* out = (float*)d_out;

    // 1) foveate (one sample/block) + where1 + weight conversions
    foveate_kernel<<<BATCH, 256>>>(x, loc, lW1, lb1, wW1, wW2, lW2);

    // 2) what layer1 -> h1w frag (+ stats partials)
    {
        dim3 grid(2, BATCH / 32);
        gemm1_kernel<<<grid, 256>>>(wb1);
    }

    // 3) finalize layer-1 BN params
    finalize1_kernel<<<256, 128>>>(wg1, wbe1, lg1, lbe1);

    // 4) both layer-2 GEMMs (BN+ReLU fused into A path, stats partials)
    {
        dim3 grid(4, BATCH / 32, 2);
        gemm2_kernel<<<grid, 256>>>(wb2, lb2);
    }

    // 5) finalize layer-2 BN params
    finalize2_kernel<<<512, 128>>>(wg2, wbe2, lg2, lbe2);

    // 6) final add + relu
    final_kernel<<<BATCH * 256 / 256, 256>>>(out);
}

// round 8
// speedup vs baseline: 1.3399x; 1.0351x over previous
#include <cuda_runtime.h>

// ---------------------------------------------------------------------------
// GlimpseNetwork fused pipeline.  B=4096, H=128, G=14, patches 14/28/56/112.
// Fragment-major tf32 MMA GEMMs; per-sample foveate writes phi frag-major.
// ---------------------------------------------------------------------------

#define BATCH 4096
#define HIMG  128
#define PHI_DIM 784

// Scratch (device globals; no cudaMalloc allowed)
__device__ __align__(16) float g_phif[PHI_DIM * BATCH];    // tf32 frag-major (A of gemm1)
__device__ __align__(16) float g_h1wf[BATCH * 128];        // f32 frag-major (A of gemm2 what)
__device__ __align__(16) float g_h1lf[BATCH * 128];        // f32 frag-major (A of gemm2 where)
__device__ __align__(16) float g_W1f[PHI_DIM * 128];       // tf32 frag-major B
__device__ __align__(16) float g_W2wf[128 * 256];
__device__ __align__(16) float g_W2lf[128 * 256];
__device__ __align__(16) float g_h2w[BATCH * 256];
__device__ __align__(16) float g_h2l[BATCH * 256];
// per-block column partials (deterministic: no atomics)
__device__ float g_p1w_s[128 * 128], g_p1w_q[128 * 128];
__device__ float g_p1l_s[32 * 128],  g_p1l_q[32 * 128];
__device__ float g_p2w_s[64 * 256],  g_p2w_q[64 * 256];
__device__ float g_p2l_s[64 * 256],  g_p2l_q[64 * 256];
// fused BN transforms: h_norm = fma(h, scale, shift)
__device__ float g_s1w[128], g_t1w[128], g_s1l[128], g_t1l[128];
__device__ float g_s2w[256], g_t2w[256], g_s2l[256], g_t2l[256];

__device__ __forceinline__ unsigned f2tf(float v) {
    unsigned r;
    asm("cvt.rna.tf32.f32 %0, %1;" : "=r"(r) : "f"(v));
    return r;
}

__device__ __forceinline__ void mma_tf32(float* d, const unsigned* a, const unsigned* b) {
    asm volatile(
        "mma.sync.aligned.m16n8k8.row.col.f32.tf32.tf32.f32 "
        "{%0,%1,%2,%3}, {%4,%5,%6,%7}, {%8,%9}, {%0,%1,%2,%3};"
        : "+f"(d[0]), "+f"(d[1]), "+f"(d[2]), "+f"(d[3])
        : "r"(a[0]), "r"(a[1]), "r"(a[2]), "r"(a[3]), "r"(b[0]), "r"(b[1]));
}

// B (weights, K x N row-major input) -> tf32 fragment-major.
__device__ __forceinline__ void conv_frag(const float* __restrict__ W,
                                          float* __restrict__ Wf,
                                          int Kw, int Nw, int tid0, int nthreads)
{
    int total = Kw * Nw;
    for (int e = tid0; e < total; e += nthreads) {
        int kk = e / Nw, n = e - kk * Nw;
        int pos = (kk >> 4) * (Nw * 16)
                + (((kk >> 3) & 1) * (Nw >> 4) + (n >> 4)) * 128
                + (((n & 7) << 2) + (kk & 3)) * 4
                + (((n >> 3) & 1) << 1) + ((kk >> 2) & 1);
        Wf[pos] = __uint_as_float(f2tf(W[e]));
    }
}

// A fragment-major word index for element (m, k), M rows total.
__device__ __forceinline__ size_t posA(int m, int k, int M)
{
    return (size_t)(k >> 4) * (M * 16)
         + (size_t)(((k >> 3) & 1) * (M >> 4) + (m >> 4)) * 128
         + (((m & 7) << 2) + (k & 3)) * 4
         + ((m >> 3) & 1) + (((k >> 2) & 1) << 1);
}

// ---------------------------------------------------------------------------
// 1) Foveate: one sample per block (4096 blocks, 256 threads), 2x2-pooled
//    pyramid in SMEM, phi written tf32 fragment-major (scatter).
//    Aux work folded into low blocks: 0..31 where-layer1 (frag out),
//    32..79 W1 conv, 80..87 W2w conv, 88..95 W2l conv.
// ---------------------------------------------------------------------------
__global__ void __launch_bounds__(256) foveate_kernel(
    const float* __restrict__ x,
    const float* __restrict__ loc,
    const float* __restrict__ lW1,
    const float* __restrict__ lb1,
    const float* __restrict__ wW1,
    const float* __restrict__ wW2,
    const float* __restrict__ lW2)
{
    __shared__ float pooled[56 * 57];
    __shared__ float center[196];
    __shared__ float wrs[256], wrq[256];
    int tid = threadIdx.x;
    int b = blockIdx.x;

    float lx = loc[2 * b + 0];
    float ly = loc[2 * b + 1];
    int cx = (int)(0.5f * ((lx + 1.0f) * 128.0f));
    int cy = (int)(0.5f * ((ly + 1.0f) * 128.0f));
    int row0 = cy - 56;
    int col0 = cx - 56;
    const float* __restrict__ img = x + (size_t)b * HIMG * HIMG;

    for (int idx = tid; idx < 56 * 56; idx += 256) {
        int pr = idx / 56;
        int pc = idx - pr * 56;
        int r = row0 + 2 * pr;
        int c = col0 + 2 * pc;
        float sm = 0.0f;
        bool r0ok = (unsigned)r < 128u, r1ok = (unsigned)(r + 1) < 128u;
        bool c0ok = (unsigned)c < 128u, c1ok = (unsigned)(c + 1) < 128u;
        if (r0ok && c0ok) sm += img[r * HIMG + c];
        if (r0ok && c1ok) sm += img[r * HIMG + c + 1];
        if (r1ok && c0ok) sm += img[(r + 1) * HIMG + c];
        if (r1ok && c1ok) sm += img[(r + 1) * HIMG + c + 1];
        pooled[pr * 57 + pc] = sm * 0.25f;
    }
    if (tid < 196) {
        int i = tid / 14;
        int j = tid - i * 14;
        int r = row0 + 49 + i;
        int c = col0 + 49 + j;
        float v = 0.0f;
        if ((unsigned)r < 128u && (unsigned)c < 128u) v = img[r * HIMG + c];
        center[tid] = v;
    }
    __syncthreads();

    for (int o = tid; o < PHI_DIM; o += 256) {
        int p = o / 196;
        int rem = o - p * 196;
        int i = rem / 14;
        int j = rem - i * 14;
        float v;
        if (p == 0) {
            v = center[rem];
        } else if (p == 1) {
            v = pooled[(21 + i) * 57 + 21 + j];
        } else if (p == 2) {
            int base = (14 + 2 * i) * 57 + 14 + 2 * j;
            v = (pooled[base] + pooled[base + 1] +
                 pooled[base + 57] + pooled[base + 58]) * 0.25f;
        } else {
            int base = (4 * i) * 57 + 4 * j;
            float sm = 0.0f;
            #pragma unroll
            for (int di = 0; di < 4; di++)
                #pragma unroll
                for (int dj = 0; dj < 4; dj++)
                    sm += pooled[base + di * 57 + dj];
            v = sm * (1.0f / 16.0f);
        }
        // fragment-major tf32 scatter write
        g_phif[posA(b, o, BATCH)] = __uint_as_float(f2tf(v));
    }

    // ---- folded aux work ----
    if (b < 32) {
        // where-layer1: block handles 128 rows, 2 row-halves; frag-major out.
        int c = tid & 127;
        int half = tid >> 7;
        int r0 = b * 128 + half * 64;
        float w0 = lW1[c], w1 = lW1[128 + c], bb = lb1[c];
        float s = 0.0f, q = 0.0f;
        for (int r = r0; r < r0 + 64; r++) {
            float2 l = ((const float2*)loc)[r];
            float v = fmaf(l.x, w0, fmaf(l.y, w1, bb));
            g_h1lf[posA(r, c, BATCH)] = v;
            s += v;
            q += v * v;
        }
        wrs[tid] = s;
        wrq[tid] = q;
        __syncthreads();
        if (tid < 128) {
            g_p1l_s[b * 128 + tid] = wrs[tid] + wrs[tid + 128];
            g_p1l_q[b * 128 + tid] = wrq[tid] + wrq[tid + 128];
        }
    } else if (b < 80) {
        conv_frag(wW1, g_W1f, PHI_DIM, 128, (b - 32) * 256 + tid, 48 * 256);
    } else if (b < 88) {
        conv_frag(wW2, g_W2wf, 128, 256, (b - 80) * 256 + tid, 8 * 256);
    } else if (b < 96) {
        conv_frag(lW2, g_W2lf, 128, 256, (b - 88) * 256 + tid, 8 * 256);
    }
}

// ---------------------------------------------------------------------------
// 2) Fragment-major pipelined tf32 MMA GEMM. 256 thr = 8 warps (2m x 4n).
//    A path: LDG.128 frag -> (optional BN/ReLU/cvt) -> STS.128 (conflict-free).
//    FRAGOUT: epilogue emits fragment-major raw f32 (+stats); else row-major.
// ---------------------------------------------------------------------------
template <bool TA, bool FRAGOUT, int K, int N, int BM, int BN, int WM, int WN>
__device__ __forceinline__ void gemm_body(const uint4* __restrict__ Af,
                                          const float4* __restrict__ Bf,
                                          const float* __restrict__ bias,
                                          const float* __restrict__ sA,
                                          const float* __restrict__ tA,
                                          float* __restrict__ Cout,
                                          float* __restrict__ ps,
                                          float* __restrict__ pq,
                                          int mb, int nb)
{
    constexpr int NB16 = BN / 16;
    constexpr int STAGE_A = BM * 16;       // floats per stage
    constexpr int STAGE_B = BN * 16;
    constexpr int STAGE = STAGE_A + STAGE_B;
    constexpr int CSS = BN + 4;
    constexpr int BUFSZ = (2 * STAGE > BM * CSS) ? 2 * STAGE : BM * CSS;
    constexpr int STEPS = K / 16;
    constexpr int SK = TA ? K : 1;
    constexpr int AUNITS = BM * 4;         // uint4 units per A stage

    __shared__ __align__(16) float buf[BUFSZ];
    __shared__ float rs[256], rq[256];
    __shared__ float sSc[SK], sSh[SK];

    int tid = threadIdx.x;
    int lane = tid & 31;
    int wid = tid >> 5;
    int wn = wid & 3;
    int wm = wid >> 2;
    int m0 = mb * BM;
    int n0 = nb * BN;

    if (TA) {
        if (tid < K) { sSc[tid] = sA[tid]; sSh[tid] = tA[tid]; }
    }
    __syncthreads();

    uint4  aReg;
    float4 bReg[BN / 64];

    auto ldA = [&](int step) {
        if (tid < AUNITS) {
            int f = tid >> 5, l = tid & 31;
            int k8 = f / (BM / 16), mt = f % (BM / 16);
            aReg = Af[(size_t)step * 16384 + (size_t)(k8 * 256 + (m0 >> 4) + mt) * 32 + l];
        }
    };
    auto ldB = [&](int step) {
        const float4* src = Bf + (size_t)step * (N * 4);
        #pragma unroll
        for (int e = 0; e < BN / 64; e++) {
            int u = tid + e * 256;
            int k8 = u / (NB16 * 32);
            int rem = u - k8 * (NB16 * 32);
            bReg[e] = src[k8 * (N / 16) * 32 + (n0 / 16) * 32 + rem];
        }
    };
    auto stA = [&](float* As, int step) {
        if (tid < AUNITS) {
            if (!TA) {
                ((uint4*)As)[tid] = aReg;
            } else {
                int f = tid >> 5, l = tid & 31;
                int k8 = f / (BM / 16);
                int kk = step * 16 + k8 * 8 + (l & 3);
                float sc0 = sSc[kk],     sh0 = sSh[kk];
                float sc4 = sSc[kk + 4], sh4 = sSh[kk + 4];
                uint4 o;
                o.x = f2tf(fmaxf(fmaf(__uint_as_float(aReg.x), sc0, sh0), 0.0f));
                o.y = f2tf(fmaxf(fmaf(__uint_as_float(aReg.y), sc0, sh0), 0.0f));
                o.z = f2tf(fmaxf(fmaf(__uint_as_float(aReg.z), sc4, sh4), 0.0f));
                o.w = f2tf(fmaxf(fmaf(__uint_as_float(aReg.w), sc4, sh4), 0.0f));
                ((uint4*)As)[tid] = o;
            }
        }
    };
    auto stB = [&](float* Bs) {
        #pragma unroll
        for (int e = 0; e < BN / 64; e++)
            ((float4*)Bs)[tid + e * 256] = bReg[e];
    };

    float acc[WM][WN][4];
    #pragma unroll
    for (int i = 0; i < WM; i++)
        #pragma unroll
        for (int f = 0; f < WN; f++)
            #pragma unroll
            for (int v = 0; v < 4; v++) acc[i][f][v] = 0.0f;

    auto compute = [&](const float* As, const float* Bs) {
        #pragma unroll
        for (int k8 = 0; k8 < 2; k8++) {
            unsigned a[WM][4];
            #pragma unroll
            for (int i = 0; i < WM; i++)
                *(uint4*)a[i] = *(const uint4*)&((const unsigned*)As)[
                    (k8 * (BM / 16) + wm * WM + i) * 128 + lane * 4];
            #pragma unroll
            for (int j = 0; j < WN / 2; j++) {
                uint4 bb = *(const uint4*)&((const unsigned*)Bs)[
                    (k8 * NB16 + wn * (WN / 2) + j) * 128 + lane * 4];
                unsigned bl[2] = {bb.x, bb.y};
                unsigned bh[2] = {bb.z, bb.w};
                #pragma unroll
                for (int i = 0; i < WM; i++) {
                    mma_tf32(acc[i][2 * j],     a[i], bl);
                    mma_tf32(acc[i][2 * j + 1], a[i], bh);
                }
            }
        }
    };

    // pipeline
    ldA(0); ldB(0);
    stA(buf, 0); stB(buf + STAGE_A);
    if (STEPS > 1) { ldA(1); ldB(1); }
    __syncthreads();

    for (int s = 0; s < STEPS; s++) {
        int cur = s & 1, nxt = cur ^ 1;
        float* curBuf = buf + cur * STAGE;
        if (s + 1 < STEPS) {
            float* nxtBuf = buf + nxt * STAGE;
            stA(nxtBuf, s + 1);
            stB(nxtBuf + STAGE_A);
        }
        if (s + 2 < STEPS) { ldA(s + 2); ldB(s + 2); }
        compute(curBuf, curBuf + STAGE_A);
        __syncthreads();
    }

    // fragments -> Cs
    float* Cs = buf;
    #pragma unroll
    for (int i = 0; i < WM; i++) {
        int row = (wm * WM + i) * 16 + (lane >> 2);
        #pragma unroll
        for (int f = 0; f < WN; f++) {
            int cb = wn * WN * 8 + f * 8 + 2 * (lane & 3);
            *(float2*)&Cs[row * CSS + cb]       = make_float2(acc[i][f][0], acc[i][f][1]);
            *(float2*)&Cs[(row + 8) * CSS + cb] = make_float2(acc[i][f][2], acc[i][f][3]);
        }
    }
    __syncthreads();

    // bias + stats (+ optional store-back for frag pass)
    {
        constexpr int RPT = BM * BN / 256;
        int c = tid & (BN - 1);
        int h = tid / BN;
        float bb = bias[n0 + c];
        float s = 0.0f, q = 0.0f;
        #pragma unroll
        for (int i = 0; i < RPT; i++) {
            int r = h * RPT + i;
            float v = Cs[r * CSS + c] + bb;
            if (FRAGOUT) Cs[r * CSS + c] = v;
            else         Cout[(size_t)(m0 + r) * N + n0 + c] = v;
            s += v;
            q += v * v;
        }
        rs[tid] = s;
        rq[tid] = q;
    }
    __syncthreads();
    if (tid < BN) {
        float s = 0.0f, q = 0.0f;
        #pragma unroll
        for (int g = 0; g < 256 / BN; g++) { s += rs[g * BN + tid]; q += rq[g * BN + tid]; }
        ps[mb * N + n0 + tid] = s;
        pq[mb * N + n0 + tid] = q;
    }

    if (FRAGOUT) {
        __syncthreads();
        // emit raw-f32 fragment-major (consumed as A by next GEMM, M=4096)
        constexpr int UNITS = BM * BN / 4;
        #pragma unroll
        for (int i2 = 0; i2 < UNITS / 256; i2++) {
            int u = tid + i2 * 256;
            int l = u & 31;
            int f = u >> 5;
            int cl = f / (2 * (BM / 16));
            int rf = f % (2 * (BM / 16));
            int k8 = rf / (BM / 16);
            int mt = rf % (BM / 16);
            int nl = cl * 16 + k8 * 8 + (l & 3);
            int rl = mt * 16 + (l >> 2);
            float4 o = make_float4(Cs[rl * CSS + nl],       Cs[(rl + 8) * CSS + nl],
                                   Cs[rl * CSS + nl + 4],   Cs[(rl + 8) * CSS + nl + 4]);
            ((float4*)Cout)[(size_t)(n0 / 16 + cl) * 16384 +
                            (size_t)(k8 * 256 + (m0 >> 4) + mt) * 32 + l] = o;
        }
    }
}

// layer-1 what GEMM: phi_frag(784x4096) -> h1w frag.  BM=32 BN=64, grid (2,128).
__global__ void __launch_bounds__(256) gemm1_kernel(const float* __restrict__ b1)
{
    gemm_body<false, true, PHI_DIM, 128, 32, 64, 1, 2>(
        (const uint4*)g_phif, (const float4*)g_W1f, b1, nullptr, nullptr,
        g_h1wf, g_p1w_s, g_p1w_q, blockIdx.y, blockIdx.x);
}

// layer-2 GEMMs merged: z=0 what, z=1 where.  BM=64 BN=128, grid (2,64,2).
__global__ void __launch_bounds__(256) gemm2_kernel(const float* __restrict__ wb2,
                                                    const float* __restrict__ lb2)
{
    if (blockIdx.z == 0)
        gemm_body<true, false, 128, 256, 64, 128, 2, 4>(
            (const uint4*)g_h1wf, (const float4*)g_W2wf, wb2, g_s1w, g_t1w,
            g_h2w, g_p2w_s, g_p2w_q, blockIdx.y, blockIdx.x);
    else
        gemm_body<true, false, 128, 256, 64, 128, 2, 4>(
            (const uint4*)g_h1lf, (const float4*)g_W2lf, lb2, g_s1l, g_t1l,
            g_h2l, g_p2l_s, g_p2l_q, blockIdx.y, blockIdx.x);
}

// ---------------------------------------------------------------------------
// 3) Parallel finalize: one block per column.
// ---------------------------------------------------------------------------
__device__ __forceinline__ void reduce_finalize(float s, float q, int c,
                                                const float* __restrict__ gam,
                                                const float* __restrict__ bet,
                                                float* __restrict__ sc_out,
                                                float* __restrict__ sh_out)
{
    __shared__ float rs[128], rq[128];
    rs[threadIdx.x] = s;
    rq[threadIdx.x] = q;
    __syncthreads();
    #pragma unroll
    for (int off = 64; off >= 32; off >>= 1) {
        if (threadIdx.x < off) {
            rs[threadIdx.x] += rs[threadIdx.x + off];
            rq[threadIdx.x] += rq[threadIdx.x + off];
        }
        __syncthreads();
    }
    if (threadIdx.x < 32) {
        float ss = rs[threadIdx.x];
        float qq = rq[threadIdx.x];
        #pragma unroll
        for (int off = 16; off > 0; off >>= 1) {
            ss += __shfl_down_sync(0xffffffffu, ss, off);
            qq += __shfl_down_sync(0xffffffffu, qq, off);
        }
        if (threadIdx.x == 0) {
            float m = ss * (1.0f / BATCH);
            float var = qq * (1.0f / BATCH) - m * m;
            float r = rsqrtf(var + 1e-5f);
            float sc = r * gam[c];
            sc_out[c] = sc;
            sh_out[c] = bet[c] - m * sc;
        }
    }
}

__global__ void finalize1_kernel(const float* __restrict__ g1w, const float* __restrict__ be1w,
                                 const float* __restrict__ g1l, const float* __restrict__ be1l)
{
    int t = threadIdx.x;
    if (blockIdx.x < 128) {
        int c = blockIdx.x;
        reduce_finalize(g_p1w_s[t * 128 + c], g_p1w_q[t * 128 + c],
                        c, g1w, be1w, g_s1w, g_t1w);
    } else {
        int c = blockIdx.x - 128;
        float s = (t < 32) ? g_p1l_s[t * 128 + c] : 0.0f;
        float q = (t < 32) ? g_p1l_q[t * 128 + c] : 0.0f;
        reduce_finalize(s, q, c, g1l, be1l, g_s1l, g_t1l);
    }
}

__global__ void finalize2_kernel(const float* __restrict__ g2w, const float* __restrict__ be2w,
                                 const float* __restrict__ g2l, const float* __restrict__ be2l)
{
    int t = threadIdx.x;
    if (blockIdx.x < 256) {
        int c = blockIdx.x;
        float s = (t < 64) ? g_p2w_s[t * 256 + c] : 0.0f;
        float q = (t < 64) ? g_p2w_q[t * 256 + c] : 0.0f;
        reduce_finalize(s, q, c, g2w, be2w, g_s2w, g_t2w);
    } else {
        int c = blockIdx.x - 256;
        float s = (t < 64) ? g_p2l_s[t * 256 + c] : 0.0f;
        float q = (t < 64) ? g_p2l_q[t * 256 + c] : 0.0f;
        reduce_finalize(s, q, c, g2l, be2l, g_s2l, g_t2l);
    }
}

// ---------------------------------------------------------------------------
// 4) Final: out = relu( BN(h2w) + BN(h2l) )
// ---------------------------------------------------------------------------
__global__ void final_kernel(float* __restrict__ out)
{
    int idx = blockIdx.x * 256 + threadIdx.x;
    int c = idx & 255;
    float vw = fmaf(g_h2w[idx], g_s2w[c], g_t2w[c]);
    float vl = fmaf(g_h2l[idx], g_s2l[c], g_t2l[c]);
    float v = vw + vl;
    out[idx] = v > 0.0f ? v : 0.0f;
}

// ---------------------------------------------------------------------------
extern "C" void kernel_launch(void* const* d_in, const int* in_sizes, int n_in,
                              void* d_out, int out_size)
{
    const float* x    = (const float*)d_in[0];
    const float* loc  = (const float*)d_in[1];
    const float* wW1  = (const float*)d_in[2];
    const float* wb1  = (const float*)d_in[3];
    const float* wg1  = (const float*)d_in[4];
    const float* wbe1 = (const float*)d_in[5];
    const float* wW2  = (const float*)d_in[6];
    const float* wb2  = (const float*)d_in[7];
    const float* wg2  = (const float*)d_in[8];
    const float* wbe2 = (const float*)d_in[9];
    const float* lW1  = (const float*)d_in[10];
    const float* lb1  = (const float*)d_in[11];
    const float* lg1  = (const float*)d_in[12];
    const float* lbe1 = (const float*)d_in[13];
    const float* lW2  = (const float*)d_in[14];
    const float* lb2  = (const float*)d_in[15];
    const float* lg2  = (const float*)d_in[16];
    const float* lbe2 = (const float*)d_in[17];
    float* out = (float*)d_out;

    // 1) foveate (one sample/block) + where1 + weight conversions
    foveate_kernel<<<BATCH, 256>>>(x, loc, lW1, lb1, wW1, wW2, lW2);

    // 2) what layer1 -> h1w frag (+ stats partials)
    {
        dim3 grid(2, BATCH / 32);
        gemm1_kernel<<<grid, 256>>>(wb1);
    }

    // 3) finalize layer-1 BN params
    finalize1_kernel<<<256, 128>>>(wg1, wbe1, lg1, lbe1);

    // 4) both layer-2 GEMMs (BN+ReLU fused into A path, stats partials)
    {
        dim3 grid(2, BATCH / 64, 2);
        gemm2_kernel<<<grid, 256>>>(wb2, lb2);
    }

    // 5) finalize layer-2 BN params
    finalize2_kernel<<<512, 128>>>(wg2, wbe2, lg2, lbe2);

    // 6) final add + relu
    final_kernel<<<BATCH * 256 / 256, 256>>>(out);
}